// round 13
// baseline (speedup 1.0000x reference)
#include <cuda_runtime.h>
#include <cstdint>

#define N 8192
#define BLOCK 256
#define CHUNKS 8          // per-thread float4 chunks: 8 * 4 * 256 = 8192 cols
#define GRID 444          // 148 SMs * 3 CTAs/SM, persistent

// ---------------------------------------------------------------------------
// Fused persistent kernel, two-pass rows:
//   pass 1: stream the W row from DRAM (default caching -> retained in L2),
//           accumulate the spike dot, DISCARD the data (no register buffer).
//   pass 2: after the block reduction, re-read the row (__ldcs, L2 HIT: the
//           chip-wide working set between the two reads is ~30MB << 126MB L2),
//           apply the STDP change, store (__stcs).
// No persistent row registers -> <=85 regs -> 3 CTAs/SM (launch_bounds).
// smem: p[N], q[N] (64 KB) -> 3 x 64 = 192 KB <= 228 KB.
// Read-stream continuity comes from TLP: ~1.5 of 3 CTAs/SM are always in
// the DRAM-read phase.
// ---------------------------------------------------------------------------
__global__ void __launch_bounds__(BLOCK, 3)
stdp_fused(const float* __restrict__ W,
           const float* __restrict__ spikes,
           const float* __restrict__ dpre,
           const float* __restrict__ membrane,
           const float* __restrict__ dfire,
           float* __restrict__ out) {
    extern __shared__ float sm[];
    float* s_p = sm;           // [N]  exp(ndp_j/20)   (== 1.0f exactly iff spike_j)
    float* s_q = sm + N;       // [N]  exp(-ndp_j/20)
    __shared__ float s_red[2][BLOCK / 32];

    const int tid = threadIdx.x;

    // Prologue: p/q into smem (deterministic recompute per CTA);
    // CTA 0 also writes the new_delta_pre output region.
    {
        float4* ndp_out4 = (float4*)(out + 2 * N);
        const float4* sp4 = (const float4*)spikes;
        const float4* dp4 = (const float4*)dpre;
#pragma unroll
        for (int t = 0; t < CHUNKS; t++) {
            int i = tid + t * BLOCK;
            float4 s = sp4[i];
            float4 d = dp4[i];
            float4 nd;
            nd.x = (s.x > 0.0f) ? 0.0f : (d.x + 1.0f);
            nd.y = (s.y > 0.0f) ? 0.0f : (d.y + 1.0f);
            nd.z = (s.z > 0.0f) ? 0.0f : (d.z + 1.0f);
            nd.w = (s.w > 0.0f) ? 0.0f : (d.w + 1.0f);
            if (blockIdx.x == 0) ndp_out4[i] = nd;
            float4 p, q;
            p.x = expf(nd.x * 0.05f);  q.x = expf(-nd.x * 0.05f);
            p.y = expf(nd.y * 0.05f);  q.y = expf(-nd.y * 0.05f);
            p.z = expf(nd.z * 0.05f);  q.z = expf(-nd.z * 0.05f);
            p.w = expf(nd.w * 0.05f);  q.w = expf(-nd.w * 0.05f);
            ((float4*)s_p)[i] = p;
            ((float4*)s_q)[i] = q;
        }
    }
    __syncthreads();

    int par = 0;
    for (int row = blockIdx.x; row < N; row += GRID) {
        const float4* wrow = (const float4*)(W + (size_t)row * N);
        float mrow  = membrane[row];   // issued early, used after barrier
        float dfrow = dfire[row];

        // ---- Pass 1: streaming dot (load -> accumulate -> discard). ----
        // spike_j == (p_j == 1.0f) exactly (exp(0) == 1).
        float4 w1[CHUNKS];
#pragma unroll
        for (int k = 0; k < CHUNKS; k++)
            w1[k] = wrow[tid + k * BLOCK];      // default policy: keep in L2
        float acc = 0.0f;
#pragma unroll
        for (int k = 0; k < CHUNKS; k++) {
            int c = tid + k * BLOCK;
            float4 p = ((const float4*)s_p)[c];
            acc += (p.x == 1.0f) ? w1[k].x : 0.0f;
            acc += (p.y == 1.0f) ? w1[k].y : 0.0f;
            acc += (p.z == 1.0f) ? w1[k].z : 0.0f;
            acc += (p.w == 1.0f) ? w1[k].w : 0.0f;
        }
#pragma unroll
        for (int o = 16; o > 0; o >>= 1)
            acc += __shfl_xor_sync(0xFFFFFFFFu, acc, o);
        if ((tid & 31) == 0) s_red[par][tid >> 5] = acc;
        __syncthreads();   // the ONLY barrier per row (s_red parity-buffered)

        float wsum = 0.0f;
#pragma unroll
        for (int i = 0; i < BLOCK / 32; i++) wsum += s_red[par][i];

        // LIF + row scalars, computed redundantly by every thread.
        float mem   = mrow * 0.99f + wsum;
        float spike = (mem > 1.0f) ? 1.0f : 0.0f;
        float nmem  = (spike > 0.0f) ? (mem - 0.8f) : mem;
        float ndf   = (spike > 0.0f) ? 0.0f : (dfrow + 1.0f);
        if (tid == 0) {
            out[row]         = spike;   // out_spikes
            out[N + row]     = nmem;    // new_membrane
            out[3 * N + row] = ndf;     // new_delta_fire
        }
        float E  = expf(ndf * 0.05f);            // comparison key (monotone)
        float ep = 0.005f * expf(-ndf * 0.05f);
        float en = 0.005f * E;

        // ---- Pass 2: re-read row (L2 hit), update, store. ----
        float4 w2[CHUNKS];
#pragma unroll
        for (int k = 0; k < CHUNKS; k++)
            w2[k] = __ldcs(&wrow[tid + k * BLOCK]);   // evict-first: done with it

        float4* orow = (float4*)(out + 4 * N + (size_t)row * N);
#pragma unroll
        for (int k = 0; k < CHUNKS; k++) {
            int c = tid + k * BLOCK;
            float4 p = ((const float4*)s_p)[c];
            float4 q = ((const float4*)s_q)[c];
            float4 o = w2[k];
            o.x += (E > p.x) ? ep * p.x : ((E < p.x) ? -en * q.x : 0.0f);
            o.y += (E > p.y) ? ep * p.y : ((E < p.y) ? -en * q.y : 0.0f);
            o.z += (E > p.z) ? ep * p.z : ((E < p.z) ? -en * q.z : 0.0f);
            o.w += (E > p.w) ? ep * p.w : ((E < p.w) ? -en * q.w : 0.0f);
            __stcs(&orow[c], o);
        }
        par ^= 1;
    }
}

// ---------------------------------------------------------------------------
// kernel_launch: inputs in metadata order
//   0: in_spikes [8192]  1: weights [8192*8192]  2: membrane [8192]
//   3: delta_pre [8192]  4: delta_fire [8192]
// out layout: [out_spikes | new_membrane | new_delta_pre | new_delta_fire | new_weights]
// ---------------------------------------------------------------------------
extern "C" void kernel_launch(void* const* d_in, const int* in_sizes, int n_in,
                              void* d_out, int out_size) {
    const float* spikes   = (const float*)d_in[0];
    const float* weights  = (const float*)d_in[1];
    const float* membrane = (const float*)d_in[2];
    const float* dpre     = (const float*)d_in[3];
    const float* dfire    = (const float*)d_in[4];
    float* out = (float*)d_out;

    (void)in_sizes; (void)n_in; (void)out_size;

    const int smem_bytes = 2 * N * sizeof(float);  // 64 KB
    cudaFuncSetAttribute(stdp_fused,
                         cudaFuncAttributeMaxDynamicSharedMemorySize, smem_bytes);

    stdp_fused<<<GRID, BLOCK, smem_bytes>>>(weights, spikes, dpre,
                                            membrane, dfire, out);
}

// round 14
// speedup vs baseline: 1.0078x; 1.0078x over previous
#include <cuda_runtime.h>
#include <cstdint>

#define N 8192
#define BLOCK 256
#define CHUNKS 8          // per-thread float4 chunks: 8 * 4 * 256 = 8192 cols
#define GRID 296          // 148 SMs * 2 CTAs/SM, persistent

// ---------------------------------------------------------------------------
// Row helpers.
// ---------------------------------------------------------------------------
__device__ __forceinline__ void load_row(float4 (&w)[CHUNKS],
                                         const float* __restrict__ W,
                                         int row, int tid) {
    const float4* wrow = (const float4*)(W + (size_t)row * N);
#pragma unroll
    for (int k = 0; k < CHUNKS; k++)
        w[k] = __ldcs(&wrow[tid + k * BLOCK]);
}

template <int PAR>
__device__ __forceinline__ void process_row(
        float4 (&w)[CHUNKS], int row,
        const float* __restrict__ s_p, const float* __restrict__ s_q,
        float (*s_red)[BLOCK / 32],
        const float* __restrict__ membrane,
        const float* __restrict__ dfire,
        float* __restrict__ out, int tid) {
    // Dot: spike_j == (p_j == 1.0f) exactly (exp(0) == 1).
    float acc = 0.0f;
#pragma unroll
    for (int k = 0; k < CHUNKS; k++) {
        int c = tid + k * BLOCK;
        float4 p = ((const float4*)s_p)[c];
        acc += (p.x == 1.0f) ? w[k].x : 0.0f;
        acc += (p.y == 1.0f) ? w[k].y : 0.0f;
        acc += (p.z == 1.0f) ? w[k].z : 0.0f;
        acc += (p.w == 1.0f) ? w[k].w : 0.0f;
    }
#pragma unroll
    for (int o = 16; o > 0; o >>= 1)
        acc += __shfl_xor_sync(0xFFFFFFFFu, acc, o);
    if ((tid & 31) == 0) s_red[PAR][tid >> 5] = acc;
    __syncthreads();   // the ONLY barrier per row (s_red parity-buffered)

    float wsum = 0.0f;
#pragma unroll
    for (int i = 0; i < BLOCK / 32; i++) wsum += s_red[PAR][i];

    // LIF + row scalars, computed redundantly by every thread.
    float mem   = membrane[row] * 0.99f + wsum;
    float spike = (mem > 1.0f) ? 1.0f : 0.0f;
    float nmem  = (spike > 0.0f) ? (mem - 0.8f) : mem;
    float ndf   = (spike > 0.0f) ? 0.0f : (dfire[row] + 1.0f);
    if (tid == 0) {
        out[row]         = spike;   // out_spikes
        out[N + row]     = nmem;    // new_membrane
        out[3 * N + row] = ndf;     // new_delta_fire
    }
    float E  = expf(ndf * 0.05f);            // comparison key (monotone transfer)
    float ep = 0.005f * expf(-ndf * 0.05f);
    float en = 0.005f * E;

    float4* orow = (float4*)(out + 4 * N + (size_t)row * N);
#pragma unroll
    for (int k = 0; k < CHUNKS; k++) {
        int c = tid + k * BLOCK;
        float4 p = ((const float4*)s_p)[c];
        float4 q = ((const float4*)s_q)[c];
        float4 o = w[k];
        o.x += (E > p.x) ? ep * p.x : ((E < p.x) ? -en * q.x : 0.0f);
        o.y += (E > p.y) ? ep * p.y : ((E < p.y) ? -en * q.y : 0.0f);
        o.z += (E > p.z) ? ep * p.z : ((E < p.z) ? -en * q.z : 0.0f);
        o.w += (E > p.w) ? ep * p.w : ((E < p.w) ? -en * q.w : 0.0f);
        __stcs(&orow[c], o);
    }
}

// ---------------------------------------------------------------------------
// Fused persistent kernel. smem: p[N], q[N] (64 KB) -> 2 CTAs/SM.
// Double-buffered register rows; main loop unrolled by 2 so buffer choice
// and s_red parity are compile-time constants (no dynamic reg indexing,
// no local-memory spills). Best-measured configuration (81.9us ncu).
// ---------------------------------------------------------------------------
__global__ void __launch_bounds__(BLOCK, 2)
stdp_fused(const float* __restrict__ W,
           const float* __restrict__ spikes,
           const float* __restrict__ dpre,
           const float* __restrict__ membrane,
           const float* __restrict__ dfire,
           float* __restrict__ out) {
    extern __shared__ float sm[];
    float* s_p = sm;           // [N]  exp(ndp_j/20)
    float* s_q = sm + N;       // [N]  exp(-ndp_j/20)
    __shared__ float s_red[2][BLOCK / 32];

    const int tid = threadIdx.x;

    // Issue first W-row loads immediately (overlap with prologue).
    float4 wA[CHUNKS], wB[CHUNKS];
    int row = blockIdx.x;
    load_row(wA, W, row, tid);

    // Prologue: p/q into smem (deterministic recompute per CTA);
    // CTA 0 also writes the new_delta_pre output region.
    {
        float4* ndp_out4 = (float4*)(out + 2 * N);
        const float4* sp4 = (const float4*)spikes;
        const float4* dp4 = (const float4*)dpre;
#pragma unroll
        for (int t = 0; t < CHUNKS; t++) {
            int i = tid + t * BLOCK;
            float4 s = sp4[i];
            float4 d = dp4[i];
            float4 nd;
            nd.x = (s.x > 0.0f) ? 0.0f : (d.x + 1.0f);
            nd.y = (s.y > 0.0f) ? 0.0f : (d.y + 1.0f);
            nd.z = (s.z > 0.0f) ? 0.0f : (d.z + 1.0f);
            nd.w = (s.w > 0.0f) ? 0.0f : (d.w + 1.0f);
            if (blockIdx.x == 0) ndp_out4[i] = nd;
            float4 p, q;
            p.x = expf(nd.x * 0.05f);  q.x = expf(-nd.x * 0.05f);
            p.y = expf(nd.y * 0.05f);  q.y = expf(-nd.y * 0.05f);
            p.z = expf(nd.z * 0.05f);  q.z = expf(-nd.z * 0.05f);
            p.w = expf(nd.w * 0.05f);  q.w = expf(-nd.w * 0.05f);
            ((float4*)s_p)[i] = p;
            ((float4*)s_q)[i] = q;
        }
    }
    __syncthreads();

    // Main loop, unrolled by 2: A-half then B-half, constant parity each.
    while (true) {
        int nrow = row + GRID;
        if (nrow < N) load_row(wB, W, nrow, tid);          // prefetch next row
        process_row<0>(wA, row, s_p, s_q, s_red, membrane, dfire, out, tid);
        row = nrow;
        if (row >= N) break;

        nrow = row + GRID;
        if (nrow < N) load_row(wA, W, nrow, tid);
        process_row<1>(wB, row, s_p, s_q, s_red, membrane, dfire, out, tid);
        row = nrow;
        if (row >= N) break;
    }
}

// ---------------------------------------------------------------------------
// kernel_launch: inputs in metadata order
//   0: in_spikes [8192]  1: weights [8192*8192]  2: membrane [8192]
//   3: delta_pre [8192]  4: delta_fire [8192]
// out layout: [out_spikes | new_membrane | new_delta_pre | new_delta_fire | new_weights]
// ---------------------------------------------------------------------------
extern "C" void kernel_launch(void* const* d_in, const int* in_sizes, int n_in,
                              void* d_out, int out_size) {
    const float* spikes   = (const float*)d_in[0];
    const float* weights  = (const float*)d_in[1];
    const float* membrane = (const float*)d_in[2];
    const float* dpre     = (const float*)d_in[3];
    const float* dfire    = (const float*)d_in[4];
    float* out = (float*)d_out;

    (void)in_sizes; (void)n_in; (void)out_size;

    const int smem_bytes = 2 * N * sizeof(float);  // 64 KB
    cudaFuncSetAttribute(stdp_fused,
                         cudaFuncAttributeMaxDynamicSharedMemorySize, smem_bytes);

    stdp_fused<<<GRID, BLOCK, smem_bytes>>>(weights, spikes, dpre,
                                            membrane, dfire, out);
}

// round 15
// speedup vs baseline: 1.0499x; 1.0418x over previous
#include <cuda_runtime.h>
#include <cstdint>

#define N 8192
#define BLOCK 256
#define CHUNKS 8          // per-thread float4 chunks: 8 * 4 * 256 = 8192 cols
#define GRID 296          // 148 SMs * 2 CTAs/SM, persistent
#define STEP (2 * GRID)   // row stride per loop iteration (pair of rows)

// ---------------------------------------------------------------------------
// Helpers.
// ---------------------------------------------------------------------------
__device__ __forceinline__ void load_row(float4 (&w)[CHUNKS],
                                         const float* __restrict__ W,
                                         int row, int tid) {
    const float4* wrow = (const float4*)(W + (size_t)row * N);
#pragma unroll
    for (int k = 0; k < CHUNKS; k++)
        w[k] = __ldcs(&wrow[tid + k * BLOCK]);
}

// Dot with 0/1 spikes: spike_j == (p_j == 1.0f) exactly (exp(0)==1).
__device__ __forceinline__ float dot_row(const float4 (&w)[CHUNKS],
                                         const float* __restrict__ s_p,
                                         int tid) {
    float acc = 0.0f;
#pragma unroll
    for (int k = 0; k < CHUNKS; k++) {
        int c = tid + k * BLOCK;
        float4 p = ((const float4*)s_p)[c];
        acc += (p.x == 1.0f) ? w[k].x : 0.0f;
        acc += (p.y == 1.0f) ? w[k].y : 0.0f;
        acc += (p.z == 1.0f) ? w[k].z : 0.0f;
        acc += (p.w == 1.0f) ? w[k].w : 0.0f;
    }
#pragma unroll
    for (int o = 16; o > 0; o >>= 1)
        acc += __shfl_xor_sync(0xFFFFFFFFu, acc, o);
    return acc;
}

// LIF scalars for one row; tid 0 writes the small outputs.
__device__ __forceinline__ void row_scalars(
        float wsum, int row,
        const float* __restrict__ membrane,
        const float* __restrict__ dfire,
        float* __restrict__ out, int tid,
        float& E, float& ep, float& en) {
    float mem   = membrane[row] * 0.99f + wsum;
    float spike = (mem > 1.0f) ? 1.0f : 0.0f;
    float nmem  = (spike > 0.0f) ? (mem - 0.8f) : mem;
    float ndf   = (spike > 0.0f) ? 0.0f : (dfire[row] + 1.0f);
    if (tid == 0) {
        out[row]         = spike;   // out_spikes
        out[N + row]     = nmem;    // new_membrane
        out[3 * N + row] = ndf;     // new_delta_fire
    }
    E  = expf(ndf * 0.05f);             // comparison key (monotone transfer)
    ep = 0.005f * expf(-ndf * 0.05f);
    en = 0.005f * E;
}

__device__ __forceinline__ float4 apply_chg(float4 o, float4 p, float4 q,
                                            float E, float ep, float en) {
    o.x += (E > p.x) ? ep * p.x : ((E < p.x) ? -en * q.x : 0.0f);
    o.y += (E > p.y) ? ep * p.y : ((E < p.y) ? -en * q.y : 0.0f);
    o.z += (E > p.z) ? ep * p.z : ((E < p.z) ? -en * q.z : 0.0f);
    o.w += (E > p.w) ? ep * p.w : ((E < p.w) ? -en * q.w : 0.0f);
    return o;
}

// ---------------------------------------------------------------------------
// Fused persistent kernel. smem: p[N], q[N] (64 KB) -> 2 CTAs/SM.
// Two rows per barrier; next-pair loads interleaved with the store stream
// (continuous moderate-rate read stream -> best sustained/throttled perf:
// benched 87.2us, the session best).
// ---------------------------------------------------------------------------
__global__ void __launch_bounds__(BLOCK, 2)
stdp_fused(const float* __restrict__ W,
           const float* __restrict__ spikes,
           const float* __restrict__ dpre,
           const float* __restrict__ membrane,
           const float* __restrict__ dfire,
           float* __restrict__ out) {
    extern __shared__ float sm[];
    float* s_p = sm;           // [N]  exp(ndp_j/20)
    float* s_q = sm + N;       // [N]  exp(-ndp_j/20)
    __shared__ float s_red[2][2][BLOCK / 32];   // [iter parity][row A/B][warp]

    const int tid = threadIdx.x;

    // Issue first pair's loads immediately (overlap with prologue).
    float4 wA[CHUNKS], wB[CHUNKS];
    int rA = blockIdx.x;
    int rB = rA + GRID;
    load_row(wA, W, rA, tid);
    load_row(wB, W, rB, tid);

    // Prologue: p/q into smem (deterministic recompute per CTA);
    // CTA 0 also writes the new_delta_pre output region.
    {
        float4* ndp_out4 = (float4*)(out + 2 * N);
        const float4* sp4 = (const float4*)spikes;
        const float4* dp4 = (const float4*)dpre;
#pragma unroll
        for (int t = 0; t < CHUNKS; t++) {
            int i = tid + t * BLOCK;
            float4 s = sp4[i];
            float4 d = dp4[i];
            float4 nd;
            nd.x = (s.x > 0.0f) ? 0.0f : (d.x + 1.0f);
            nd.y = (s.y > 0.0f) ? 0.0f : (d.y + 1.0f);
            nd.z = (s.z > 0.0f) ? 0.0f : (d.z + 1.0f);
            nd.w = (s.w > 0.0f) ? 0.0f : (d.w + 1.0f);
            if (blockIdx.x == 0) ndp_out4[i] = nd;
            float4 p, q;
            p.x = expf(nd.x * 0.05f);  q.x = expf(-nd.x * 0.05f);
            p.y = expf(nd.y * 0.05f);  q.y = expf(-nd.y * 0.05f);
            p.z = expf(nd.z * 0.05f);  q.z = expf(-nd.z * 0.05f);
            p.w = expf(nd.w * 0.05f);  q.w = expf(-nd.w * 0.05f);
            ((float4*)s_p)[i] = p;
            ((float4*)s_q)[i] = q;
        }
    }
    __syncthreads();

    int par = 0;
    while (rA < N) {
        const bool hasB = (rB < N);

        // Dots for both rows; ONE barrier serves the pair.
        float accA = dot_row(wA, s_p, tid);
        float accB = hasB ? dot_row(wB, s_p, tid) : 0.0f;
        if ((tid & 31) == 0) {
            s_red[par][0][tid >> 5] = accA;
            s_red[par][1][tid >> 5] = accB;
        }
        __syncthreads();

        float wsumA = 0.0f, wsumB = 0.0f;
#pragma unroll
        for (int i = 0; i < BLOCK / 32; i++) {
            wsumA += s_red[par][0][i];
            wsumB += s_red[par][1][i];
        }

        float EA, epA, enA, EB = 0, epB = 0, enB = 0;
        row_scalars(wsumA, rA, membrane, dfire, out, tid, EA, epA, enA);
        if (hasB)
            row_scalars(wsumB, rB, membrane, dfire, out, tid, EB, epB, enB);

        const int nA = rA + STEP;
        const int nB = rB + STEP;
        const bool loadA = (nA < N);
        const bool loadB = (nB < N);
        float4* orowA = (float4*)(out + 4 * N + (size_t)rA * N);
        float4* orowB = (float4*)(out + 4 * N + (size_t)rB * N);
        const float4* nrowA = (const float4*)(W + (size_t)(loadA ? nA : 0) * N);
        const float4* nrowB = (const float4*)(W + (size_t)(loadB ? nB : 0) * N);

        // Write both rows; refill each freed register chunk immediately with
        // the next pair's data so the read stream never drains.
#pragma unroll
        for (int k = 0; k < CHUNKS; k++) {
            int c = tid + k * BLOCK;
            float4 p = ((const float4*)s_p)[c];
            float4 q = ((const float4*)s_q)[c];
            __stcs(&orowA[c], apply_chg(wA[k], p, q, EA, epA, enA));
            if (loadA) wA[k] = __ldcs(&nrowA[c]);
            if (hasB) {
                __stcs(&orowB[c], apply_chg(wB[k], p, q, EB, epB, enB));
                if (loadB) wB[k] = __ldcs(&nrowB[c]);
            }
        }

        rA = nA;
        rB = nB;
        par ^= 1;
    }
}

// ---------------------------------------------------------------------------
// kernel_launch: inputs in metadata order
//   0: in_spikes [8192]  1: weights [8192*8192]  2: membrane [8192]
//   3: delta_pre [8192]  4: delta_fire [8192]
// out layout: [out_spikes | new_membrane | new_delta_pre | new_delta_fire | new_weights]
// ---------------------------------------------------------------------------
extern "C" void kernel_launch(void* const* d_in, const int* in_sizes, int n_in,
                              void* d_out, int out_size) {
    const float* spikes   = (const float*)d_in[0];
    const float* weights  = (const float*)d_in[1];
    const float* membrane = (const float*)d_in[2];
    const float* dpre     = (const float*)d_in[3];
    const float* dfire    = (const float*)d_in[4];
    float* out = (float*)d_out;

    (void)in_sizes; (void)n_in; (void)out_size;

    const int smem_bytes = 2 * N * sizeof(float);  // 64 KB
    cudaFuncSetAttribute(stdp_fused,
                         cudaFuncAttributeMaxDynamicSharedMemorySize, smem_bytes);

    stdp_fused<<<GRID, BLOCK, smem_bytes>>>(weights, spikes, dpre,
                                            membrane, dfire, out);
}